// round 1
// baseline (speedup 1.0000x reference)
#include <cuda_runtime.h>
#include <math.h>

#define DIM     768
#define NHEADS  12
#define HD      64
#define BATCH   8
#define SEQ     1024
#define MROWS   (BATCH*SEQ)     /* 8192 */
#define QKVN    (3*DIM)         /* 2304 */
#define SCALE   0.125f          /* 64^-0.5 */

// Scratch (allocation-free rule: __device__ globals)
__device__ float g_qkv[(size_t)MROWS * QKVN];   // [B*N, 3*DIM]  (q|k|v per row)
__device__ float g_att[(size_t)MROWS * DIM];    // [B*N, DIM]    (b,n,h,hd layout)

// ---------------------------------------------------------------------------
// GEMM: C[M,N] = A[M,K] @ W[K,N] + bias[N]
// 128x128 block tile, BK=16, 256 threads, 8x8 micro-tile.
// Rows contiguous (ty*8+i); cols strided (tx + 16*j) so B-fragment smem reads
// are conflict-free scalar loads and C stores are coalesced over tx.
// ---------------------------------------------------------------------------
__global__ __launch_bounds__(256)
void gemm_bias_kernel(const float* __restrict__ A, const float* __restrict__ W,
                      const float* __restrict__ bias, float* __restrict__ C,
                      int M, int N, int K)
{
    __shared__ float As[16][132];   // transposed: As[k][m], pad 132 (16B-aligned rows)
    __shared__ float Bs[16][132];   // Bs[k][n]

    const int tid = threadIdx.x;
    const int tx  = tid & 15;
    const int ty  = tid >> 4;
    const int bm  = blockIdx.y * 128;
    const int bn  = blockIdx.x * 128;

    const int a_r = tid >> 2;          // 0..63 (two passes of 64 rows)
    const int a_c = (tid & 3) << 2;    // 0,4,8,12
    const int b_r = tid >> 5;          // 0..7 (two passes of 8 k-rows)
    const int b_c = (tid & 31) << 2;   // 0..124

    float acc[8][8];
    #pragma unroll
    for (int i = 0; i < 8; i++)
        #pragma unroll
        for (int j = 0; j < 8; j++) acc[i][j] = 0.f;

    for (int k0 = 0; k0 < K; k0 += 16) {
        #pragma unroll
        for (int p = 0; p < 2; p++) {
            int r = a_r + p * 64;
            float4 v = *(const float4*)&A[(size_t)(bm + r) * K + k0 + a_c];
            As[a_c + 0][r] = v.x;
            As[a_c + 1][r] = v.y;
            As[a_c + 2][r] = v.z;
            As[a_c + 3][r] = v.w;
        }
        #pragma unroll
        for (int p = 0; p < 2; p++) {
            int r = b_r + p * 8;
            *(float4*)&Bs[r][b_c] =
                *(const float4*)&W[(size_t)(k0 + r) * N + bn + b_c];
        }
        __syncthreads();

        #pragma unroll
        for (int k = 0; k < 16; k++) {
            float ar[8], br[8];
            float4 a0 = *(const float4*)&As[k][ty * 8];
            float4 a1 = *(const float4*)&As[k][ty * 8 + 4];
            ar[0] = a0.x; ar[1] = a0.y; ar[2] = a0.z; ar[3] = a0.w;
            ar[4] = a1.x; ar[5] = a1.y; ar[6] = a1.z; ar[7] = a1.w;
            #pragma unroll
            for (int j = 0; j < 8; j++) br[j] = Bs[k][tx + 16 * j];
            #pragma unroll
            for (int i = 0; i < 8; i++)
                #pragma unroll
                for (int j = 0; j < 8; j++)
                    acc[i][j] += ar[i] * br[j];
        }
        __syncthreads();
    }

    #pragma unroll
    for (int j = 0; j < 8; j++) {
        float bb = bias[bn + tx + 16 * j];
        #pragma unroll
        for (int i = 0; i < 8; i++)
            C[(size_t)(bm + ty * 8 + i) * N + bn + tx + 16 * j] = acc[i][j] + bb;
    }
}

// ---------------------------------------------------------------------------
// Flash attention: one block = (b, h, 64-query tile). 256 threads.
// 64x64 K/V tiles streamed through SMEM, online softmax, O accum in regs.
// Thread (ty,tx): rows ty*4..+3, S-cols tx+16j, O-dims tx+16jj.
// Row-group = 16 lanes within a half-warp -> shfl_xor 8/4/2/1 reductions.
// ---------------------------------------------------------------------------
__global__ __launch_bounds__(256)
void attn_kernel()
{
    extern __shared__ float sm[];
    float* Qs = sm;                 // [64][68], pre-scaled by SCALE
    float* Ks = sm + 64 * 68;       // [64][68]
    float* Vs = sm + 2 * 64 * 68;   // [64][68]
    float* Ps = sm + 3 * 64 * 68;   // [64][68]

    const int tid = threadIdx.x;
    const int tx  = tid & 15;
    const int ty  = tid >> 4;
    const int b   = blockIdx.y / NHEADS;
    const int h   = blockIdx.y % NHEADS;
    const int q0  = blockIdx.x * 64;

    const float* base = g_qkv + (size_t)b * SEQ * QKVN + h * HD;

    const int lr = tid >> 4;          // 0..15
    const int ld = (tid & 15) << 2;   // 0..60

    // Load Q tile (scaled)
    #pragma unroll
    for (int p = 0; p < 4; p++) {
        int row = p * 16 + lr;
        float4 v = *(const float4*)(base + (size_t)(q0 + row) * QKVN + ld);
        v.x *= SCALE; v.y *= SCALE; v.z *= SCALE; v.w *= SCALE;
        *(float4*)&Qs[row * 68 + ld] = v;
    }

    float m_i[4], l_i[4], acc[4][4];
    #pragma unroll
    for (int i = 0; i < 4; i++) {
        m_i[i] = -INFINITY;
        l_i[i] = 0.f;
        #pragma unroll
        for (int jj = 0; jj < 4; jj++) acc[i][jj] = 0.f;
    }

    for (int kt = 0; kt < SEQ / 64; kt++) {
        const float* kb = base + (size_t)(kt * 64) * QKVN;
        #pragma unroll
        for (int p = 0; p < 4; p++) {
            int row = p * 16 + lr;
            *(float4*)&Ks[row * 68 + ld] =
                *(const float4*)(kb + (size_t)row * QKVN + DIM + ld);
            *(float4*)&Vs[row * 68 + ld] =
                *(const float4*)(kb + (size_t)row * QKVN + 2 * DIM + ld);
        }
        __syncthreads();

        // S = Q K^T (Q pre-scaled)
        float s[4][4];
        #pragma unroll
        for (int i = 0; i < 4; i++)
            #pragma unroll
            for (int j = 0; j < 4; j++) s[i][j] = 0.f;

        #pragma unroll
        for (int d4 = 0; d4 < 16; d4++) {
            float4 q[4], kk[4];
            #pragma unroll
            for (int i = 0; i < 4; i++)
                q[i] = *(const float4*)&Qs[(ty * 4 + i) * 68 + d4 * 4];
            #pragma unroll
            for (int j = 0; j < 4; j++)
                kk[j] = *(const float4*)&Ks[(tx + 16 * j) * 68 + d4 * 4];
            #pragma unroll
            for (int i = 0; i < 4; i++)
                #pragma unroll
                for (int j = 0; j < 4; j++)
                    s[i][j] += q[i].x * kk[j].x + q[i].y * kk[j].y
                             + q[i].z * kk[j].z + q[i].w * kk[j].w;
        }

        // Online softmax per row (replicated across the 16-lane row group)
        #pragma unroll
        for (int i = 0; i < 4; i++) {
            float mloc = fmaxf(fmaxf(s[i][0], s[i][1]), fmaxf(s[i][2], s[i][3]));
            #pragma unroll
            for (int o = 8; o >= 1; o >>= 1)
                mloc = fmaxf(mloc, __shfl_xor_sync(0xffffffffu, mloc, o));
            float mn    = fmaxf(m_i[i], mloc);
            float alpha = __expf(m_i[i] - mn);
            m_i[i] = mn;
            float p0 = __expf(s[i][0] - mn);
            float p1 = __expf(s[i][1] - mn);
            float p2 = __expf(s[i][2] - mn);
            float p3 = __expf(s[i][3] - mn);
            float ssum = (p0 + p1) + (p2 + p3);
            #pragma unroll
            for (int o = 8; o >= 1; o >>= 1)
                ssum += __shfl_xor_sync(0xffffffffu, ssum, o);
            l_i[i] = l_i[i] * alpha + ssum;
            #pragma unroll
            for (int jj = 0; jj < 4; jj++) acc[i][jj] *= alpha;
            Ps[(ty * 4 + i) * 68 + tx]      = p0;
            Ps[(ty * 4 + i) * 68 + tx + 16] = p1;
            Ps[(ty * 4 + i) * 68 + tx + 32] = p2;
            Ps[(ty * 4 + i) * 68 + tx + 48] = p3;
        }
        __syncthreads();

        // O += P @ V
        #pragma unroll 4
        for (int j = 0; j < 64; j++) {
            float pv[4], vv[4];
            #pragma unroll
            for (int i = 0; i < 4; i++)
                pv[i] = Ps[(ty * 4 + i) * 68 + j];
            #pragma unroll
            for (int jj = 0; jj < 4; jj++)
                vv[jj] = Vs[j * 68 + tx + 16 * jj];
            #pragma unroll
            for (int i = 0; i < 4; i++)
                #pragma unroll
                for (int jj = 0; jj < 4; jj++)
                    acc[i][jj] += pv[i] * vv[jj];
        }
        __syncthreads();
    }

    // Normalize and write out in [B*N, DIM] layout (col = h*64 + d)
    #pragma unroll
    for (int i = 0; i < 4; i++) {
        float inv = 1.f / l_i[i];
        int row = q0 + ty * 4 + i;
        float* op = g_att + (size_t)(b * SEQ + row) * DIM + h * HD;
        #pragma unroll
        for (int jj = 0; jj < 4; jj++)
            op[tx + 16 * jj] = acc[i][jj] * inv;
    }
}

// ---------------------------------------------------------------------------
extern "C" void kernel_launch(void* const* d_in, const int* in_sizes, int n_in,
                              void* d_out, int out_size)
{
    const float* x      = (const float*)d_in[0];
    const float* w_qkv  = (const float*)d_in[1];
    const float* b_qkv  = (const float*)d_in[2];
    const float* w_proj = (const float*)d_in[3];
    const float* b_proj = (const float*)d_in[4];
    float* out = (float*)d_out;

    float* qkv = nullptr;
    float* att = nullptr;
    cudaGetSymbolAddress((void**)&qkv, g_qkv);
    cudaGetSymbolAddress((void**)&att, g_att);

    const int smem_bytes = 4 * 64 * 68 * (int)sizeof(float);  // 69,632 B
    cudaFuncSetAttribute(attn_kernel,
                         cudaFuncAttributeMaxDynamicSharedMemorySize, smem_bytes);

    // 1) QKV projection: [8192,768] @ [768,2304] + bias
    gemm_bias_kernel<<<dim3(QKVN / 128, MROWS / 128), 256>>>(
        x, w_qkv, b_qkv, qkv, MROWS, QKVN, DIM);

    // 2) Flash attention per (b, h, 64-query tile)
    attn_kernel<<<dim3(SEQ / 64, BATCH * NHEADS), 256, smem_bytes>>>();

    // 3) Output projection: [8192,768] @ [768,768] + bias
    gemm_bias_kernel<<<dim3(DIM / 128, MROWS / 128), 256>>>(
        att, w_proj, b_proj, out, MROWS, DIM, DIM);
}

// round 4
// speedup vs baseline: 1.5062x; 1.5062x over previous
#include <cuda_runtime.h>
#include <math.h>
#include <stdint.h>

#define DIM     768
#define NHEADS  12
#define HD      64
#define BATCH   8
#define SEQ     1024
#define MROWS   (BATCH*SEQ)     /* 8192 */
#define QKVN    (3*DIM)         /* 2304 */
#define SCALE   0.125f          /* 64^-0.5 */
#define GK      768
#define NCHUNK  24

// Scratch (allocation-free rule: __device__ globals)
__device__ __align__(1024) float g_qkv[(size_t)MROWS * QKVN];   // [B*N, 3*DIM]
__device__ __align__(1024) float g_att[(size_t)MROWS * DIM];    // [B*N, DIM]

__device__ __forceinline__ uint32_t smem_u32(const void* p) {
    uint32_t a;
    asm("{ .reg .u64 t; cvta.to.shared.u64 t, %1; cvt.u32.u64 %0, t; }"
        : "=r"(a) : "l"(p));
    return a;
}
__device__ __forceinline__ uint32_t f2tf32(float f) {
    uint32_t u;
    asm("cvt.rna.tf32.f32 %0, %1;" : "=r"(u) : "f"(f));
    return u;
}
__device__ __forceinline__ void mma_tf32(float* c, const uint32_t* a,
                                         const uint32_t* b) {
    asm volatile(
        "mma.sync.aligned.m16n8k8.row.col.f32.tf32.tf32.f32 "
        "{%0,%1,%2,%3}, {%4,%5,%6,%7}, {%8,%9}, {%0,%1,%2,%3};"
        : "+f"(c[0]), "+f"(c[1]), "+f"(c[2]), "+f"(c[3])
        : "r"(a[0]), "r"(a[1]), "r"(a[2]), "r"(a[3]), "r"(b[0]), "r"(b[1]));
}

// ===========================================================================
// tf32 mma.sync GEMM: C[M,N] = A[M,768] @ W[768,N] + bias
// 128x128x32 tile, 256 threads, 8 warps (2m x 4n), 64x32 warp tile.
// SMEM holds fragment-native layouts (one LDS.128 / LDS.64 per fragment).
// Double-buffered, register-staged global loads, one sync per chunk.
// ===========================================================================
__global__ __launch_bounds__(256, 1)
void gemm_mma(const float* __restrict__ A, const float* __restrict__ W,
              const float* __restrict__ bias, float* __restrict__ C, int N)
{
    extern __shared__ float sm[];
    const uint32_t sbase = smem_u32(sm);
    const int tid  = threadIdx.x;
    const int lane = tid & 31, wid = tid >> 5;
    const int wm   = wid >> 2, wn = wid & 3;
    const int bm   = blockIdx.y * 128, bn = blockIdx.x * 128;

    float acc[4][4][4];
    #pragma unroll
    for (int mi = 0; mi < 4; mi++)
        #pragma unroll
        for (int ni = 0; ni < 4; ni++)
            #pragma unroll
            for (int r = 0; r < 4; r++) acc[mi][ni][r] = 0.f;

    int a_row[4], a_c0[4], b_k[4], b_n0[4];
    #pragma unroll
    for (int i = 0; i < 4; i++) {
        int idx = i * 256 + tid;
        a_row[i] = idx >> 3;            // 0..127
        a_c0[i]  = (idx & 7) * 4;       // 0..28
        b_k[i]   = idx >> 5;            // 0..31
        b_n0[i]  = (idx & 31) * 4;      // 0..124
    }

    float4 ga[4], gb[4];

    #define LOADG(c)                                                          \
        do {                                                                  \
            _Pragma("unroll")                                                 \
            for (int i = 0; i < 4; i++)                                       \
                ga[i] = *(const float4*)&A[(size_t)(bm + a_row[i]) * GK       \
                                           + (c) * 32 + a_c0[i]];             \
            _Pragma("unroll")                                                 \
            for (int i = 0; i < 4; i++)                                       \
                gb[i] = *(const float4*)&W[(size_t)((c) * 32 + b_k[i]) * N    \
                                           + bn + b_n0[i]];                   \
        } while (0)

    #define STORES(s)                                                         \
        do {                                                                  \
            const uint32_t sA = sbase + (uint32_t)(s) * 32768u;               \
            const uint32_t sB = sA + 16384u;                                  \
            _Pragma("unroll")                                                 \
            for (int i = 0; i < 4; i++) {                                     \
                int row = a_row[i], c0 = a_c0[i];                             \
                int kt = c0 >> 3, c8hi = (c0 & 4) >> 2;                       \
                int mt = row >> 4, r8 = row & 15;                             \
                uint32_t tb = (uint32_t)((kt * 8 + mt) << 9);                 \
                uint32_t sw = (uint32_t)((kt << 5) ^ ((r8 & 2) << 3));        \
                uint32_t reg = (uint32_t)((r8 >> 3) + 2 * c8hi);              \
                float v[4] = {ga[i].x, ga[i].y, ga[i].z, ga[i].w};            \
                _Pragma("unroll")                                             \
                for (int j = 0; j < 4; j++) {                                 \
                    uint32_t ln = (uint32_t)(((r8 & 7) * 4 + j));             \
                    uint32_t off = (tb + (ln << 4) + (reg << 2)) ^ sw;        \
                    asm volatile("st.shared.b32 [%0], %1;"                    \
                                 :: "r"(sA + off), "r"(f2tf32(v[j]))          \
                                 : "memory");                                 \
                }                                                             \
            }                                                                 \
            _Pragma("unroll")                                                 \
            for (int i = 0; i < 4; i++) {                                     \
                int k = b_k[i], n0 = b_n0[i];                                 \
                int kt = k >> 3, k8 = k & 7;                                  \
                uint32_t reg = (uint32_t)(k8 >> 2);                           \
                uint32_t k3  = (uint32_t)(k8 & 3);                            \
                float v[4] = {gb[i].x, gb[i].y, gb[i].z, gb[i].w};            \
                _Pragma("unroll")                                             \
                for (int j = 0; j < 4; j++) {                                 \
                    int n = n0 + j, nt = n >> 3, n8 = n & 7;                  \
                    uint32_t off = (uint32_t)(((kt * 16 + nt) << 8)           \
                                 + ((n8 * 4 + (int)k3) << 3) + (reg << 2));   \
                    off ^= (uint32_t)(nt << 3);                               \
                    asm volatile("st.shared.b32 [%0], %1;"                    \
                                 :: "r"(sB + off), "r"(f2tf32(v[j]))          \
                                 : "memory");                                 \
                }                                                             \
            }                                                                 \
        } while (0)

    LOADG(0);
    STORES(0);
    __syncthreads();

    for (int c = 0; c < NCHUNK; c++) {
        if (c + 1 < NCHUNK) LOADG(c + 1);

        const uint32_t sA = sbase + (uint32_t)(c & 1) * 32768u;
        const uint32_t sB = sA + 16384u;
        #pragma unroll
        for (int ks = 0; ks < 4; ks++) {
            uint32_t af[4][4], bf[4][2];
            #pragma unroll
            for (int mi = 0; mi < 4; mi++) {
                uint32_t off = (uint32_t)(((ks * 8 + wm * 4 + mi) << 9)
                             + (lane << 4));
                off ^= (uint32_t)((ks << 5) ^ ((lane & 8) << 1));
                asm volatile("ld.shared.v4.b32 {%0,%1,%2,%3}, [%4];"
                             : "=r"(af[mi][0]), "=r"(af[mi][1]),
                               "=r"(af[mi][2]), "=r"(af[mi][3])
                             : "r"(sA + off));
            }
            #pragma unroll
            for (int ni = 0; ni < 4; ni++) {
                int bnt = wn * 4 + ni;
                uint32_t off = (uint32_t)(((ks * 16 + bnt) << 8) + (lane << 3));
                off ^= (uint32_t)(bnt << 3);
                asm volatile("ld.shared.v2.b32 {%0,%1}, [%2];"
                             : "=r"(bf[ni][0]), "=r"(bf[ni][1])
                             : "r"(sB + off));
            }
            #pragma unroll
            for (int mi = 0; mi < 4; mi++)
                #pragma unroll
                for (int ni = 0; ni < 4; ni++)
                    mma_tf32(acc[mi][ni], af[mi], bf[ni]);
        }

        if (c + 1 < NCHUNK) STORES((c + 1) & 1);   // FIXED: was STORES(c+1)
        __syncthreads();
    }

    // epilogue: bias + store (float2 per fragment half)
    #pragma unroll
    for (int mi = 0; mi < 4; mi++) {
        int row = bm + wm * 64 + mi * 16 + (lane >> 2);
        #pragma unroll
        for (int ni = 0; ni < 4; ni++) {
            int col = bn + wn * 32 + ni * 8 + (lane & 3) * 2;
            float2 bb = *(const float2*)&bias[col];
            float2 o0, o1;
            o0.x = acc[mi][ni][0] + bb.x;
            o0.y = acc[mi][ni][1] + bb.y;
            o1.x = acc[mi][ni][2] + bb.x;
            o1.y = acc[mi][ni][3] + bb.y;
            *(float2*)&C[(size_t)row * N + col]       = o0;
            *(float2*)&C[(size_t)(row + 8) * N + col] = o1;
        }
    }
    #undef LOADG
    #undef STORES
}

// ---------------------------------------------------------------------------
// Flash attention (round-1 version): one block = (b, h, 64-query tile).
// ---------------------------------------------------------------------------
__global__ __launch_bounds__(256)
void attn_kernel()
{
    extern __shared__ float sm[];
    float* Qs = sm;
    float* Ks = sm + 64 * 68;
    float* Vs = sm + 2 * 64 * 68;
    float* Ps = sm + 3 * 64 * 68;

    const int tid = threadIdx.x;
    const int tx  = tid & 15;
    const int ty  = tid >> 4;
    const int b   = blockIdx.y / NHEADS;
    const int h   = blockIdx.y % NHEADS;
    const int q0  = blockIdx.x * 64;

    const float* base = g_qkv + (size_t)b * SEQ * QKVN + h * HD;

    const int lr = tid >> 4;
    const int ld = (tid & 15) << 2;

    #pragma unroll
    for (int p = 0; p < 4; p++) {
        int row = p * 16 + lr;
        float4 v = *(const float4*)(base + (size_t)(q0 + row) * QKVN + ld);
        v.x *= SCALE; v.y *= SCALE; v.z *= SCALE; v.w *= SCALE;
        *(float4*)&Qs[row * 68 + ld] = v;
    }

    float m_i[4], l_i[4], acc[4][4];
    #pragma unroll
    for (int i = 0; i < 4; i++) {
        m_i[i] = -INFINITY;
        l_i[i] = 0.f;
        #pragma unroll
        for (int jj = 0; jj < 4; jj++) acc[i][jj] = 0.f;
    }

    for (int kt = 0; kt < SEQ / 64; kt++) {
        const float* kb = base + (size_t)(kt * 64) * QKVN;
        #pragma unroll
        for (int p = 0; p < 4; p++) {
            int row = p * 16 + lr;
            *(float4*)&Ks[row * 68 + ld] =
                *(const float4*)(kb + (size_t)row * QKVN + DIM + ld);
            *(float4*)&Vs[row * 68 + ld] =
                *(const float4*)(kb + (size_t)row * QKVN + 2 * DIM + ld);
        }
        __syncthreads();

        float s[4][4];
        #pragma unroll
        for (int i = 0; i < 4; i++)
            #pragma unroll
            for (int j = 0; j < 4; j++) s[i][j] = 0.f;

        #pragma unroll
        for (int d4 = 0; d4 < 16; d4++) {
            float4 q[4], kk[4];
            #pragma unroll
            for (int i = 0; i < 4; i++)
                q[i] = *(const float4*)&Qs[(ty * 4 + i) * 68 + d4 * 4];
            #pragma unroll
            for (int j = 0; j < 4; j++)
                kk[j] = *(const float4*)&Ks[(tx + 16 * j) * 68 + d4 * 4];
            #pragma unroll
            for (int i = 0; i < 4; i++)
                #pragma unroll
                for (int j = 0; j < 4; j++)
                    s[i][j] += q[i].x * kk[j].x + q[i].y * kk[j].y
                             + q[i].z * kk[j].z + q[i].w * kk[j].w;
        }

        #pragma unroll
        for (int i = 0; i < 4; i++) {
            float mloc = fmaxf(fmaxf(s[i][0], s[i][1]), fmaxf(s[i][2], s[i][3]));
            #pragma unroll
            for (int o = 8; o >= 1; o >>= 1)
                mloc = fmaxf(mloc, __shfl_xor_sync(0xffffffffu, mloc, o));
            float mn    = fmaxf(m_i[i], mloc);
            float alpha = __expf(m_i[i] - mn);
            m_i[i] = mn;
            float p0 = __expf(s[i][0] - mn);
            float p1 = __expf(s[i][1] - mn);
            float p2 = __expf(s[i][2] - mn);
            float p3 = __expf(s[i][3] - mn);
            float ssum = (p0 + p1) + (p2 + p3);
            #pragma unroll
            for (int o = 8; o >= 1; o >>= 1)
                ssum += __shfl_xor_sync(0xffffffffu, ssum, o);
            l_i[i] = l_i[i] * alpha + ssum;
            #pragma unroll
            for (int jj = 0; jj < 4; jj++) acc[i][jj] *= alpha;
            Ps[(ty * 4 + i) * 68 + tx]      = p0;
            Ps[(ty * 4 + i) * 68 + tx + 16] = p1;
            Ps[(ty * 4 + i) * 68 + tx + 32] = p2;
            Ps[(ty * 4 + i) * 68 + tx + 48] = p3;
        }
        __syncthreads();

        #pragma unroll 4
        for (int j = 0; j < 64; j++) {
            float pv[4], vv[4];
            #pragma unroll
            for (int i = 0; i < 4; i++)
                pv[i] = Ps[(ty * 4 + i) * 68 + j];
            #pragma unroll
            for (int jj = 0; jj < 4; jj++)
                vv[jj] = Vs[j * 68 + tx + 16 * jj];
            #pragma unroll
            for (int i = 0; i < 4; i++)
                #pragma unroll
                for (int jj = 0; jj < 4; jj++)
                    acc[i][jj] += pv[i] * vv[jj];
        }
        __syncthreads();
    }

    #pragma unroll
    for (int i = 0; i < 4; i++) {
        float inv = 1.f / l_i[i];
        int row = q0 + ty * 4 + i;
        float* op = g_att + (size_t)(b * SEQ + row) * DIM + h * HD;
        #pragma unroll
        for (int jj = 0; jj < 4; jj++)
            op[tx + 16 * jj] = acc[i][jj] * inv;
    }
}

// ---------------------------------------------------------------------------
extern "C" void kernel_launch(void* const* d_in, const int* in_sizes, int n_in,
                              void* d_out, int out_size)
{
    const float* x      = (const float*)d_in[0];
    const float* w_qkv  = (const float*)d_in[1];
    const float* b_qkv  = (const float*)d_in[2];
    const float* w_proj = (const float*)d_in[3];
    const float* b_proj = (const float*)d_in[4];
    float* out = (float*)d_out;

    float* qkv = nullptr;
    float* att = nullptr;
    cudaGetSymbolAddress((void**)&qkv, g_qkv);
    cudaGetSymbolAddress((void**)&att, g_att);

    const int gemm_smem = 65536;
    const int attn_smem = 4 * 64 * 68 * (int)sizeof(float);
    cudaFuncSetAttribute(gemm_mma,
                         cudaFuncAttributeMaxDynamicSharedMemorySize, gemm_smem);
    cudaFuncSetAttribute(attn_kernel,
                         cudaFuncAttributeMaxDynamicSharedMemorySize, attn_smem);

    // 1) QKV projection: [8192,768] @ [768,2304] + bias   (tf32 mma.sync)
    gemm_mma<<<dim3(QKVN / 128, MROWS / 128), 256, gemm_smem>>>(
        x, w_qkv, b_qkv, qkv, QKVN);

    // 2) Flash attention
    attn_kernel<<<dim3(SEQ / 64, BATCH * NHEADS), 256, attn_smem>>>();

    // 3) Output projection: [8192,768] @ [768,768] + bias (tf32 mma.sync)
    gemm_mma<<<dim3(DIM / 128, MROWS / 128), 256, gemm_smem>>>(
        att, w_proj, b_proj, out, DIM);
}

// round 5
// speedup vs baseline: 2.5054x; 1.6634x over previous
#include <cuda_runtime.h>
#include <math.h>
#include <stdint.h>

#define DIM     768
#define NHEADS  12
#define HD      64
#define BATCH   8
#define SEQ     1024
#define MROWS   (BATCH*SEQ)     /* 8192 */
#define QKVN    (3*DIM)         /* 2304 */
#define SC2     0.1803368801111244f   /* 64^-0.5 * log2(e) */
#define GK      768
#define NCHUNK  24

// Scratch (allocation-free rule: __device__ globals)
__device__ __align__(1024) float g_qkv[(size_t)MROWS * QKVN];   // [B*N, 3*DIM]
__device__ __align__(1024) float g_att[(size_t)MROWS * DIM];    // [B*N, DIM]

__device__ __forceinline__ uint32_t smem_u32(const void* p) {
    uint32_t a;
    asm("{ .reg .u64 t; cvta.to.shared.u64 t, %1; cvt.u32.u64 %0, t; }"
        : "=r"(a) : "l"(p));
    return a;
}
__device__ __forceinline__ uint32_t f2tf32(float f) {
    uint32_t u;
    asm("cvt.rna.tf32.f32 %0, %1;" : "=r"(u) : "f"(f));
    return u;
}
__device__ __forceinline__ float ex2(float x) {
    float r;
    asm("ex2.approx.ftz.f32 %0, %1;" : "=f"(r) : "f"(x));
    return r;
}
__device__ __forceinline__ void mma_tf32(float* c, const uint32_t* a,
                                         const uint32_t* b) {
    asm volatile(
        "mma.sync.aligned.m16n8k8.row.col.f32.tf32.tf32.f32 "
        "{%0,%1,%2,%3}, {%4,%5,%6,%7}, {%8,%9}, {%0,%1,%2,%3};"
        : "+f"(c[0]), "+f"(c[1]), "+f"(c[2]), "+f"(c[3])
        : "r"(a[0]), "r"(a[1]), "r"(a[2]), "r"(a[3]), "r"(b[0]), "r"(b[1]));
}

// ===========================================================================
// tf32 mma.sync GEMM (validated round 4): C[M,N] = A[M,768] @ W[768,N] + bias
// ===========================================================================
__global__ __launch_bounds__(256, 1)
void gemm_mma(const float* __restrict__ A, const float* __restrict__ W,
              const float* __restrict__ bias, float* __restrict__ C, int N)
{
    extern __shared__ float sm[];
    const uint32_t sbase = smem_u32(sm);
    const int tid  = threadIdx.x;
    const int lane = tid & 31, wid = tid >> 5;
    const int wm   = wid >> 2, wn = wid & 3;
    const int bm   = blockIdx.y * 128, bn = blockIdx.x * 128;

    float acc[4][4][4];
    #pragma unroll
    for (int mi = 0; mi < 4; mi++)
        #pragma unroll
        for (int ni = 0; ni < 4; ni++)
            #pragma unroll
            for (int r = 0; r < 4; r++) acc[mi][ni][r] = 0.f;

    int a_row[4], a_c0[4], b_k[4], b_n0[4];
    #pragma unroll
    for (int i = 0; i < 4; i++) {
        int idx = i * 256 + tid;
        a_row[i] = idx >> 3;
        a_c0[i]  = (idx & 7) * 4;
        b_k[i]   = idx >> 5;
        b_n0[i]  = (idx & 31) * 4;
    }

    float4 ga[4], gb[4];

    #define LOADG(c)                                                          \
        do {                                                                  \
            _Pragma("unroll")                                                 \
            for (int i = 0; i < 4; i++)                                       \
                ga[i] = *(const float4*)&A[(size_t)(bm + a_row[i]) * GK       \
                                           + (c) * 32 + a_c0[i]];             \
            _Pragma("unroll")                                                 \
            for (int i = 0; i < 4; i++)                                       \
                gb[i] = *(const float4*)&W[(size_t)((c) * 32 + b_k[i]) * N    \
                                           + bn + b_n0[i]];                   \
        } while (0)

    #define STORES(s)                                                         \
        do {                                                                  \
            const uint32_t sA = sbase + (uint32_t)(s) * 32768u;               \
            const uint32_t sB = sA + 16384u;                                  \
            _Pragma("unroll")                                                 \
            for (int i = 0; i < 4; i++) {                                     \
                int row = a_row[i], c0 = a_c0[i];                             \
                int kt = c0 >> 3, c8hi = (c0 & 4) >> 2;                       \
                int mt = row >> 4, r8 = row & 15;                             \
                uint32_t tb = (uint32_t)((kt * 8 + mt) << 9);                 \
                uint32_t sw = (uint32_t)((kt << 5) ^ ((r8 & 2) << 3));        \
                uint32_t reg = (uint32_t)((r8 >> 3) + 2 * c8hi);              \
                float v[4] = {ga[i].x, ga[i].y, ga[i].z, ga[i].w};            \
                _Pragma("unroll")                                             \
                for (int j = 0; j < 4; j++) {                                 \
                    uint32_t ln = (uint32_t)(((r8 & 7) * 4 + j));             \
                    uint32_t off = (tb + (ln << 4) + (reg << 2)) ^ sw;        \
                    asm volatile("st.shared.b32 [%0], %1;"                    \
                                 :: "r"(sA + off), "r"(f2tf32(v[j]))          \
                                 : "memory");                                 \
                }                                                             \
            }                                                                 \
            _Pragma("unroll")                                                 \
            for (int i = 0; i < 4; i++) {                                     \
                int k = b_k[i], n0 = b_n0[i];                                 \
                int kt = k >> 3, k8 = k & 7;                                  \
                uint32_t reg = (uint32_t)(k8 >> 2);                           \
                uint32_t k3  = (uint32_t)(k8 & 3);                            \
                float v[4] = {gb[i].x, gb[i].y, gb[i].z, gb[i].w};            \
                _Pragma("unroll")                                             \
                for (int j = 0; j < 4; j++) {                                 \
                    int n = n0 + j, nt = n >> 3, n8 = n & 7;                  \
                    uint32_t off = (uint32_t)(((kt * 16 + nt) << 8)           \
                                 + ((n8 * 4 + (int)k3) << 3) + (reg << 2));   \
                    off ^= (uint32_t)(nt << 3);                               \
                    asm volatile("st.shared.b32 [%0], %1;"                    \
                                 :: "r"(sB + off), "r"(f2tf32(v[j]))          \
                                 : "memory");                                 \
                }                                                             \
            }                                                                 \
        } while (0)

    LOADG(0);
    STORES(0);
    __syncthreads();

    for (int c = 0; c < NCHUNK; c++) {
        if (c + 1 < NCHUNK) LOADG(c + 1);

        const uint32_t sA = sbase + (uint32_t)(c & 1) * 32768u;
        const uint32_t sB = sA + 16384u;
        #pragma unroll
        for (int ks = 0; ks < 4; ks++) {
            uint32_t af[4][4], bf[4][2];
            #pragma unroll
            for (int mi = 0; mi < 4; mi++) {
                uint32_t off = (uint32_t)(((ks * 8 + wm * 4 + mi) << 9)
                             + (lane << 4));
                off ^= (uint32_t)((ks << 5) ^ ((lane & 8) << 1));
                asm volatile("ld.shared.v4.b32 {%0,%1,%2,%3}, [%4];"
                             : "=r"(af[mi][0]), "=r"(af[mi][1]),
                               "=r"(af[mi][2]), "=r"(af[mi][3])
                             : "r"(sA + off));
            }
            #pragma unroll
            for (int ni = 0; ni < 4; ni++) {
                int bnt = wn * 4 + ni;
                uint32_t off = (uint32_t)(((ks * 16 + bnt) << 8) + (lane << 3));
                off ^= (uint32_t)(bnt << 3);
                asm volatile("ld.shared.v2.b32 {%0,%1}, [%2];"
                             : "=r"(bf[ni][0]), "=r"(bf[ni][1])
                             : "r"(sB + off));
            }
            #pragma unroll
            for (int mi = 0; mi < 4; mi++)
                #pragma unroll
                for (int ni = 0; ni < 4; ni++)
                    mma_tf32(acc[mi][ni], af[mi], bf[ni]);
        }

        if (c + 1 < NCHUNK) STORES((c + 1) & 1);
        __syncthreads();
    }

    #pragma unroll
    for (int mi = 0; mi < 4; mi++) {
        int row = bm + wm * 64 + mi * 16 + (lane >> 2);
        #pragma unroll
        for (int ni = 0; ni < 4; ni++) {
            int col = bn + wn * 32 + ni * 8 + (lane & 3) * 2;
            float2 bb = *(const float2*)&bias[col];
            float2 o0, o1;
            o0.x = acc[mi][ni][0] + bb.x;
            o0.y = acc[mi][ni][1] + bb.y;
            o1.x = acc[mi][ni][2] + bb.x;
            o1.y = acc[mi][ni][3] + bb.y;
            *(float2*)&C[(size_t)row * N + col]       = o0;
            *(float2*)&C[(size_t)(row + 8) * N + col] = o1;
        }
    }
    #undef LOADG
    #undef STORES
}

// ===========================================================================
// Tensor-core flash attention. CTA = (b, h, 64-q tile), 128 threads (4 warps).
// Warp w owns q rows [w*16, w*16+16). Online softmax in exp2 domain.
// SMEM: Ks (b-frag native, 16KB) | Vs (V^T b-frag native, 16KB) | Ps (16KB).
// K/V word(nt,ks,lane,j) = (nt*8+ks)*64 + ((lane*2+j)^(ks<<2))
// P   word(row,cc)       = row*64 + ((nt*8 + (cc&3)*2 + ((cc>>2)&1)) ^ ((row&3)<<3))
// ===========================================================================
__global__ __launch_bounds__(128)
void attn_mma()
{
    extern __shared__ uint32_t smu[];
    const uint32_t sb  = smem_u32(smu);
    const uint32_t KsB = sb, VsB = sb + 16384u, PsB = sb + 32768u;

    const int tid  = threadIdx.x;
    const int lane = tid & 31, w = tid >> 5;
    const int b    = blockIdx.y / NHEADS;
    const int h    = blockIdx.y % NHEADS;
    const int q0   = blockIdx.x * 64;

    const float* base = g_qkv + (size_t)b * SEQ * QKVN + h * HD;

    // ---- Q into registers as A-fragments (pre-scaled to exp2 domain) ----
    const int r0w = w * 16 + (lane >> 2);     // CTA-local q row (0..63)
    const int c0  = lane & 3;
    uint32_t qa[8][4];
    {
        const float* Qp0 = base + (size_t)(q0 + r0w) * QKVN;
        const float* Qp1 = Qp0 + 8 * QKVN;
        #pragma unroll
        for (int ks = 0; ks < 8; ks++) {
            qa[ks][0] = f2tf32(Qp0[ks * 8 + c0]     * SC2);
            qa[ks][1] = f2tf32(Qp1[ks * 8 + c0]     * SC2);
            qa[ks][2] = f2tf32(Qp0[ks * 8 + c0 + 4] * SC2);
            qa[ks][3] = f2tf32(Qp1[ks * 8 + c0 + 4] * SC2);
        }
    }

    float oacc[8][4];
    #pragma unroll
    for (int nt = 0; nt < 8; nt++)
        #pragma unroll
        for (int r = 0; r < 4; r++) oacc[nt][r] = 0.f;
    float m0 = -INFINITY, m1 = -INFINITY, l0 = 0.f, l1 = 0.f;

    // P-store positions (per lane constants)
    const int cc0 = 2 * c0, cc1 = cc0 + 1;
    const uint32_t pos0 = (uint32_t)((cc0 & 3) * 2 + (cc0 >> 2));
    const uint32_t pos1 = (uint32_t)((cc1 & 3) * 2 + (cc1 >> 2));
    const uint32_t swz  = (uint32_t)((r0w & 3) << 3);
    const uint32_t prow0 = PsB + (uint32_t)r0w * 256u;
    const uint32_t prow1 = prow0 + 8u * 256u;

    // K/V fill coordinates
    const int krr = tid >> 4, kd0 = (tid & 15) * 4;      // K: 8 rows/pass
    const int vrr = tid & 31, vd0 = (tid >> 5) * 4;      // V: 32 rows/pass

    for (int kt = 0; kt < SEQ / 64; kt++) {
        __syncthreads();   // prev iter's PV (reads Vs) must finish

        // ---- fill K tile (b-frag native for QK^T: n=kv, k=hd) ----
        {
            const float* Kg = base + DIM + (size_t)(kt * 64) * QKVN;
            float4 t[8];
            #pragma unroll
            for (int p = 0; p < 8; p++)
                t[p] = *(const float4*)(Kg + (size_t)(p * 8 + krr) * QKVN + kd0);
            #pragma unroll
            for (int p = 0; p < 8; p++) {
                int r = p * 8 + krr;
                float v[4] = {t[p].x, t[p].y, t[p].z, t[p].w};
                #pragma unroll
                for (int e = 0; e < 4; e++) {
                    int d = kd0 + e;
                    uint32_t ln   = (uint32_t)(((r & 7) << 2) | (d & 3));
                    uint32_t word = (uint32_t)(((r >> 3) * 8 + (d >> 3)) << 6)
                                  + ((ln * 2u + (uint32_t)((d >> 2) & 1))
                                     ^ (uint32_t)((d >> 3) << 2));
                    asm volatile("st.shared.b32 [%0], %1;"
                                 :: "r"(KsB + word * 4u), "r"(f2tf32(v[e]))
                                 : "memory");
                }
            }
        }
        // ---- fill V^T tile (b-frag native for PV: n=hd, k=kv) ----
        {
            const float* Vg = base + 2 * DIM + (size_t)(kt * 64) * QKVN;
            float4 t[8];
            #pragma unroll
            for (int p = 0; p < 8; p++) {
                int r  = (p & 1) * 32 + vrr;
                int d0 = (p >> 1) * 16 + vd0;
                t[p] = *(const float4*)(Vg + (size_t)r * QKVN + d0);
            }
            #pragma unroll
            for (int p = 0; p < 8; p++) {
                int r  = (p & 1) * 32 + vrr;
                int d0 = (p >> 1) * 16 + vd0;
                float v[4] = {t[p].x, t[p].y, t[p].z, t[p].w};
                #pragma unroll
                for (int e = 0; e < 4; e++) {
                    int d = d0 + e;
                    uint32_t ln   = (uint32_t)(((d & 7) << 2) | (r & 3));
                    uint32_t word = (uint32_t)(((d >> 3) * 8 + (r >> 3)) << 6)
                                  + ((ln * 2u + (uint32_t)((r >> 2) & 1))
                                     ^ (uint32_t)((r >> 3) << 2));
                    asm volatile("st.shared.b32 [%0], %1;"
                                 :: "r"(VsB + word * 4u), "r"(f2tf32(v[e]))
                                 : "memory");
                }
            }
        }
        __syncthreads();

        // ---- S = Q K^T ----
        float sacc[8][4];
        #pragma unroll
        for (int nt = 0; nt < 8; nt++)
            #pragma unroll
            for (int r = 0; r < 4; r++) sacc[nt][r] = 0.f;

        #pragma unroll
        for (int ks = 0; ks < 8; ks++) {
            uint32_t bf[8][2];
            #pragma unroll
            for (int nt = 0; nt < 8; nt++) {
                uint32_t off = (uint32_t)((nt * 8 + ks) << 6)
                             + (((uint32_t)lane * 2u) ^ (uint32_t)(ks << 2));
                asm volatile("ld.shared.v2.b32 {%0,%1}, [%2];"
                             : "=r"(bf[nt][0]), "=r"(bf[nt][1])
                             : "r"(KsB + off * 4u));
            }
            #pragma unroll
            for (int nt = 0; nt < 8; nt++)
                mma_tf32(sacc[nt], qa[ks], bf[nt]);
        }

        // ---- online softmax (exp2 domain) ----
        float mx0 = -INFINITY, mx1 = -INFINITY;
        #pragma unroll
        for (int nt = 0; nt < 8; nt++) {
            mx0 = fmaxf(mx0, fmaxf(sacc[nt][0], sacc[nt][1]));
            mx1 = fmaxf(mx1, fmaxf(sacc[nt][2], sacc[nt][3]));
        }
        mx0 = fmaxf(mx0, __shfl_xor_sync(0xffffffffu, mx0, 1));
        mx0 = fmaxf(mx0, __shfl_xor_sync(0xffffffffu, mx0, 2));
        mx1 = fmaxf(mx1, __shfl_xor_sync(0xffffffffu, mx1, 1));
        mx1 = fmaxf(mx1, __shfl_xor_sync(0xffffffffu, mx1, 2));
        float mn0 = fmaxf(m0, mx0), mn1 = fmaxf(m1, mx1);
        float a0 = ex2(m0 - mn0), a1 = ex2(m1 - mn1);
        m0 = mn0; m1 = mn1;
        l0 *= a0;  l1 *= a1;

        float sum0 = 0.f, sum1 = 0.f;
        #pragma unroll
        for (int nt = 0; nt < 8; nt++) {
            float p00 = ex2(sacc[nt][0] - m0);
            float p01 = ex2(sacc[nt][1] - m0);
            float p10 = ex2(sacc[nt][2] - m1);
            float p11 = ex2(sacc[nt][3] - m1);
            sum0 += p00 + p01;
            sum1 += p10 + p11;
            oacc[nt][0] *= a0; oacc[nt][1] *= a0;
            oacc[nt][2] *= a1; oacc[nt][3] *= a1;
            uint32_t nb = (uint32_t)(nt * 8);
            asm volatile("st.shared.b32 [%0], %1;"
                         :: "r"(prow0 + ((nb + pos0) ^ swz) * 4u),
                            "r"(f2tf32(p00)) : "memory");
            asm volatile("st.shared.b32 [%0], %1;"
                         :: "r"(prow0 + ((nb + pos1) ^ swz) * 4u),
                            "r"(f2tf32(p01)) : "memory");
            asm volatile("st.shared.b32 [%0], %1;"
                         :: "r"(prow1 + ((nb + pos0) ^ swz) * 4u),
                            "r"(f2tf32(p10)) : "memory");
            asm volatile("st.shared.b32 [%0], %1;"
                         :: "r"(prow1 + ((nb + pos1) ^ swz) * 4u),
                            "r"(f2tf32(p11)) : "memory");
        }
        sum0 += __shfl_xor_sync(0xffffffffu, sum0, 1);
        sum0 += __shfl_xor_sync(0xffffffffu, sum0, 2);
        sum1 += __shfl_xor_sync(0xffffffffu, sum1, 1);
        sum1 += __shfl_xor_sync(0xffffffffu, sum1, 2);
        l0 += sum0; l1 += sum1;

        // ---- O += P V  (P rows are warp-private: no barrier needed) ----
        #pragma unroll
        for (int ks = 0; ks < 8; ks++) {
            uint32_t pa[4];
            uint32_t wo = (((uint32_t)(ks * 8 + c0 * 2)) ^ swz) * 4u;
            asm volatile("ld.shared.v2.b32 {%0,%1}, [%2];"
                         : "=r"(pa[0]), "=r"(pa[2]) : "r"(prow0 + wo));
            asm volatile("ld.shared.v2.b32 {%0,%1}, [%2];"
                         : "=r"(pa[1]), "=r"(pa[3]) : "r"(prow1 + wo));
            #pragma unroll
            for (int nt = 0; nt < 8; nt++) {
                uint32_t vb[2];
                uint32_t off = (uint32_t)((nt * 8 + ks) << 6)
                             + (((uint32_t)lane * 2u) ^ (uint32_t)(ks << 2));
                asm volatile("ld.shared.v2.b32 {%0,%1}, [%2];"
                             : "=r"(vb[0]), "=r"(vb[1]) : "r"(VsB + off * 4u));
                mma_tf32(oacc[nt], pa, vb);
            }
        }
    }

    // ---- normalize, write out [B*N, DIM] (col = h*64 + d) ----
    {
        float inv0 = 1.f / l0, inv1 = 1.f / l1;
        float* O0 = g_att + (size_t)(b * SEQ + q0 + r0w) * DIM + h * HD;
        float* O1 = O0 + 8 * DIM;
        #pragma unroll
        for (int nt = 0; nt < 8; nt++) {
            int col = nt * 8 + cc0;
            float2 v0 = {oacc[nt][0] * inv0, oacc[nt][1] * inv0};
            float2 v1 = {oacc[nt][2] * inv1, oacc[nt][3] * inv1};
            *(float2*)(O0 + col) = v0;
            *(float2*)(O1 + col) = v1;
        }
    }
}

// ---------------------------------------------------------------------------
extern "C" void kernel_launch(void* const* d_in, const int* in_sizes, int n_in,
                              void* d_out, int out_size)
{
    const float* x      = (const float*)d_in[0];
    const float* w_qkv  = (const float*)d_in[1];
    const float* b_qkv  = (const float*)d_in[2];
    const float* w_proj = (const float*)d_in[3];
    const float* b_proj = (const float*)d_in[4];
    float* out = (float*)d_out;

    float* qkv = nullptr;
    float* att = nullptr;
    cudaGetSymbolAddress((void**)&qkv, g_qkv);
    cudaGetSymbolAddress((void**)&att, g_att);

    const int gemm_smem = 65536;
    const int attn_smem = 49152;
    cudaFuncSetAttribute(gemm_mma,
                         cudaFuncAttributeMaxDynamicSharedMemorySize, gemm_smem);
    cudaFuncSetAttribute(attn_mma,
                         cudaFuncAttributeMaxDynamicSharedMemorySize, attn_smem);

    // 1) QKV projection: [8192,768] @ [768,2304] + bias   (tf32 mma.sync)
    gemm_mma<<<dim3(QKVN / 128, MROWS / 128), 256, gemm_smem>>>(
        x, w_qkv, b_qkv, qkv, QKVN);

    // 2) Tensor-core flash attention
    attn_mma<<<dim3(SEQ / 64, BATCH * NHEADS), 128, attn_smem>>>();

    // 3) Output projection: [8192,768] @ [768,768] + bias (tf32 mma.sync)
    gemm_mma<<<dim3(DIM / 128, MROWS / 128), 256, gemm_smem>>>(
        att, w_proj, b_proj, out, DIM);
}